// round 1
// baseline (speedup 1.0000x reference)
#include <cuda_runtime.h>
#include <math.h>

// ---------------------------------------------------------------------------
// GCN_77893526880285: 2-layer GCN on GB300
//   layer l: support = X @ Wl ; agg[v] = sum_{e: dst=v} w_e * support[src_e] ; +b
//   x1 = relu(layer1), x2 = log_softmax(layer2)
// Strategy: build CSR-by-dst once per launch (histogram + scan + scatter),
// then atomic-free warp-per-node aggregation; fp32 tiled SGEMM for the GEMMs.
// ---------------------------------------------------------------------------

#define NMAX 100352
#define EMAX 1600000
#define HMAX 128
#define DMAX 64
#define NCHUNK_MAX 128
#define SCAN_BLOCK 1024

__device__ float g_support1[(size_t)NMAX * HMAX];   // 51.2 MB
__device__ float g_support2[(size_t)NMAX * DMAX];   // 25.6 MB
__device__ int   g_counts[NMAX];
__device__ int   g_rowoff[NMAX + 1];
__device__ int   g_cursor[NMAX];
__device__ int   g_srcs[EMAX];
__device__ float g_ws[EMAX];
__device__ int   g_csum[NCHUNK_MAX];
__device__ int   g_coff[NCHUNK_MAX];

// ---------------------------- CSR build ------------------------------------

__global__ void zero_counts_kernel(int* __restrict__ counts, int N) {
    int i = blockIdx.x * blockDim.x + threadIdx.x;
    if (i < N) counts[i] = 0;
}

__global__ void hist_kernel(const int* __restrict__ dst, int* __restrict__ counts, int E) {
    int i = blockIdx.x * blockDim.x + threadIdx.x;
    if (i < E) atomicAdd(&counts[dst[i]], 1);
}

__global__ void chunk_sum_kernel(const int* __restrict__ counts, int* __restrict__ csum, int N) {
    int i = blockIdx.x * SCAN_BLOCK + threadIdx.x;
    int v = (i < N) ? counts[i] : 0;
    #pragma unroll
    for (int o = 16; o; o >>= 1) v += __shfl_xor_sync(0xffffffffu, v, o);
    __shared__ int ws[32];
    if ((threadIdx.x & 31) == 0) ws[threadIdx.x >> 5] = v;
    __syncthreads();
    if (threadIdx.x < 32) {
        int x = ws[threadIdx.x];
        #pragma unroll
        for (int o = 16; o; o >>= 1) x += __shfl_xor_sync(0xffffffffu, x, o);
        if (threadIdx.x == 0) csum[blockIdx.x] = x;
    }
}

// scan the (<=128) chunk sums; one block of 128 threads
__global__ void chunk_scan_kernel(const int* __restrict__ csum, int* __restrict__ coff,
                                  int* __restrict__ rowoff, int nch, int N) {
    int tid = threadIdx.x;
    int v = (tid < nch) ? csum[tid] : 0;
    int lane = tid & 31, wid = tid >> 5;
    int x = v;
    #pragma unroll
    for (int o = 1; o < 32; o <<= 1) { int t = __shfl_up_sync(0xffffffffu, x, o); if (lane >= o) x += t; }
    __shared__ int ws[4];
    if (lane == 31) ws[wid] = x;
    __syncthreads();
    int base = 0;
    #pragma unroll
    for (int w = 0; w < 4; w++) if (w < wid) base += ws[w];
    int excl = base + x - v;
    if (tid < nch) coff[tid] = excl;
    if (tid == nch - 1) rowoff[N] = excl + v;
}

__global__ void scan_apply_kernel(const int* __restrict__ counts, const int* __restrict__ coff,
                                  int* __restrict__ rowoff, int* __restrict__ cursor, int N) {
    int tid = threadIdx.x, b = blockIdx.x;
    int i = b * SCAN_BLOCK + tid;
    int v = (i < N) ? counts[i] : 0;
    int lane = tid & 31, wid = tid >> 5;
    int x = v;
    #pragma unroll
    for (int o = 1; o < 32; o <<= 1) { int t = __shfl_up_sync(0xffffffffu, x, o); if (lane >= o) x += t; }
    __shared__ int ws[32];
    if (lane == 31) ws[wid] = x;
    __syncthreads();
    if (wid == 0) {
        int y = ws[lane];
        #pragma unroll
        for (int o = 1; o < 32; o <<= 1) { int t = __shfl_up_sync(0xffffffffu, y, o); if (lane >= o) y += t; }
        ws[lane] = y;
    }
    __syncthreads();
    int base = coff[b] + (wid ? ws[wid - 1] : 0);
    int excl = base + x - v;
    if (i < N) { rowoff[i] = excl; cursor[i] = excl; }
}

__global__ void scatter_kernel(const int* __restrict__ src, const int* __restrict__ dst,
                               const float* __restrict__ ew, int* __restrict__ cursor,
                               int* __restrict__ s_sorted, float* __restrict__ w_sorted, int E) {
    int i = blockIdx.x * blockDim.x + threadIdx.x;
    if (i < E) {
        int d = dst[i];
        int p = atomicAdd(&cursor[d], 1);
        s_sorted[p] = src[i];
        w_sorted[p] = ew[i];
    }
}

// ---------------------------- SGEMM ----------------------------------------

template<int BM, int BN, int BK, int TM, int TN>
__global__ void sgemm_kernel(const float* __restrict__ A, const float* __restrict__ B,
                             float* __restrict__ C, int M, int N, int K) {
    constexpr int THREADS = (BM / TM) * (BN / TN);
    __shared__ float As[BK][BM + 4];   // +4 keeps rows 16B-aligned (BM+4 is mult of 4)
    __shared__ float Bs[BK][BN];
    const int tid = threadIdx.x;
    const int tx = tid % (BN / TN);
    const int ty = tid / (BN / TN);
    const int rowBase = blockIdx.y * BM;
    const int colBase = blockIdx.x * BN;
    float acc[TM][TN] = {};
    constexpr int A_ITERS = BM * BK / (THREADS * 4);
    constexpr int B_ITERS = BK * BN / (THREADS * 4);

    for (int k0 = 0; k0 < K; k0 += BK) {
        #pragma unroll
        for (int it = 0; it < A_ITERS; it++) {
            int idx = (tid + it * THREADS) * 4;
            int r = idx / BK;
            int kk = idx % BK;
            int gr = rowBase + r;
            float4 v = make_float4(0.f, 0.f, 0.f, 0.f);
            if (gr < M) v = *reinterpret_cast<const float4*>(&A[(size_t)gr * K + k0 + kk]);
            As[kk + 0][r] = v.x; As[kk + 1][r] = v.y; As[kk + 2][r] = v.z; As[kk + 3][r] = v.w;
        }
        #pragma unroll
        for (int it = 0; it < B_ITERS; it++) {
            int idx = (tid + it * THREADS) * 4;
            int kk = idx / BN;
            int c  = idx % BN;
            *reinterpret_cast<float4*>(&Bs[kk][c]) =
                *reinterpret_cast<const float4*>(&B[(size_t)(k0 + kk) * N + colBase + c]);
        }
        __syncthreads();
        #pragma unroll
        for (int kk = 0; kk < BK; kk++) {
            float ar[TM], br[TN];
            #pragma unroll
            for (int i = 0; i < TM; i += 4) {
                float4 v = *reinterpret_cast<const float4*>(&As[kk][ty * TM + i]);
                ar[i] = v.x; ar[i + 1] = v.y; ar[i + 2] = v.z; ar[i + 3] = v.w;
            }
            #pragma unroll
            for (int j = 0; j < TN; j += 4) {
                float4 v = *reinterpret_cast<const float4*>(&Bs[kk][tx * TN + j]);
                br[j] = v.x; br[j + 1] = v.y; br[j + 2] = v.z; br[j + 3] = v.w;
            }
            #pragma unroll
            for (int i = 0; i < TM; i++)
                #pragma unroll
                for (int j = 0; j < TN; j++)
                    acc[i][j] = fmaf(ar[i], br[j], acc[i][j]);
        }
        __syncthreads();
    }
    #pragma unroll
    for (int i = 0; i < TM; i++) {
        int gr = rowBase + ty * TM + i;
        if (gr < M) {
            #pragma unroll
            for (int j = 0; j < TN; j += 4) {
                float4 v = make_float4(acc[i][j], acc[i][j + 1], acc[i][j + 2], acc[i][j + 3]);
                *reinterpret_cast<float4*>(&C[(size_t)gr * N + colBase + tx * TN + j]) = v;
            }
        }
    }
}

// ------------------------ Aggregation (warp per node) -----------------------

// layer 1: H=128 features, lane holds 4 floats; + bias, relu, write to d_out
__global__ void agg1_kernel(const float* __restrict__ support, const int* __restrict__ rowoff,
                            const int* __restrict__ srcs, const float* __restrict__ ws,
                            const float* __restrict__ bias, float* __restrict__ out, int N) {
    int gw = (blockIdx.x * blockDim.x + threadIdx.x) >> 5;
    int lane = threadIdx.x & 31;
    if (gw >= N) return;
    int s = rowoff[gw], e = rowoff[gw + 1];
    float4 acc = make_float4(0.f, 0.f, 0.f, 0.f);
    int j = s;
    int cs = 0; float cw = 0.f;
    if (j < e) { cs = srcs[j]; cw = ws[j]; }
    while (j < e) {
        int nj = j + 1; int ns = 0; float nw = 0.f;
        if (nj < e) { ns = srcs[nj]; nw = ws[nj]; }   // prefetch next edge
        float4 v = *reinterpret_cast<const float4*>(&support[(size_t)cs * 128 + lane * 4]);
        acc.x = fmaf(cw, v.x, acc.x);
        acc.y = fmaf(cw, v.y, acc.y);
        acc.z = fmaf(cw, v.z, acc.z);
        acc.w = fmaf(cw, v.w, acc.w);
        cs = ns; cw = nw; j = nj;
    }
    float4 bb = *reinterpret_cast<const float4*>(&bias[lane * 4]);
    acc.x = fmaxf(acc.x + bb.x, 0.f);
    acc.y = fmaxf(acc.y + bb.y, 0.f);
    acc.z = fmaxf(acc.z + bb.z, 0.f);
    acc.w = fmaxf(acc.w + bb.w, 0.f);
    *reinterpret_cast<float4*>(&out[(size_t)gw * 128 + lane * 4]) = acc;
}

// layer 2: D=64 features, lane holds 2 floats; + bias, log_softmax, write to d_out
__global__ void agg2_kernel(const float* __restrict__ support, const int* __restrict__ rowoff,
                            const int* __restrict__ srcs, const float* __restrict__ ws,
                            const float* __restrict__ bias, float* __restrict__ out, int N) {
    int gw = (blockIdx.x * blockDim.x + threadIdx.x) >> 5;
    int lane = threadIdx.x & 31;
    if (gw >= N) return;
    int s = rowoff[gw], e = rowoff[gw + 1];
    float2 acc = make_float2(0.f, 0.f);
    int j = s;
    int cs = 0; float cw = 0.f;
    if (j < e) { cs = srcs[j]; cw = ws[j]; }
    while (j < e) {
        int nj = j + 1; int ns = 0; float nw = 0.f;
        if (nj < e) { ns = srcs[nj]; nw = ws[nj]; }
        float2 v = *reinterpret_cast<const float2*>(&support[(size_t)cs * 64 + lane * 2]);
        acc.x = fmaf(cw, v.x, acc.x);
        acc.y = fmaf(cw, v.y, acc.y);
        cs = ns; cw = nw; j = nj;
    }
    float2 bb = *reinterpret_cast<const float2*>(&bias[lane * 2]);
    acc.x += bb.x; acc.y += bb.y;
    // log_softmax over 64 values (2 per lane)
    float m = fmaxf(acc.x, acc.y);
    #pragma unroll
    for (int o = 16; o; o >>= 1) m = fmaxf(m, __shfl_xor_sync(0xffffffffu, m, o));
    float es = expf(acc.x - m) + expf(acc.y - m);
    #pragma unroll
    for (int o = 16; o; o >>= 1) es += __shfl_xor_sync(0xffffffffu, es, o);
    float ls = m + logf(es);
    float2 r = make_float2(acc.x - ls, acc.y - ls);
    *reinterpret_cast<float2*>(&out[(size_t)gw * 64 + lane * 2]) = r;
}

// ---------------------------- launch ----------------------------------------

extern "C" void kernel_launch(void* const* d_in, const int* in_sizes, int n_in,
                              void* d_out, int out_size) {
    const float* feature = (const float*)d_in[0];
    const int*   src     = (const int*)d_in[1];
    const int*   dst     = (const int*)d_in[2];
    const float* ew      = (const float*)d_in[3];
    const float* W1      = (const float*)d_in[4];
    const float* b1      = (const float*)d_in[5];
    const float* W2      = (const float*)d_in[6];
    const float* b2      = (const float*)d_in[7];
    float* out = (float*)d_out;

    const int E    = in_sizes[1];
    const int H    = in_sizes[5];            // 128
    const int F_IN = in_sizes[4] / H;        // 256
    const int D    = in_sizes[7];            // 64
    const int N    = in_sizes[0] / F_IN;     // 100000

    float* x1 = out;                          // [N, H]
    float* x2 = out + (size_t)N * H;          // [N, D]

    void *p_sup1, *p_sup2, *p_counts, *p_rowoff, *p_cursor, *p_srcs, *p_ws, *p_csum, *p_coff;
    cudaGetSymbolAddress(&p_sup1,   g_support1);
    cudaGetSymbolAddress(&p_sup2,   g_support2);
    cudaGetSymbolAddress(&p_counts, g_counts);
    cudaGetSymbolAddress(&p_rowoff, g_rowoff);
    cudaGetSymbolAddress(&p_cursor, g_cursor);
    cudaGetSymbolAddress(&p_srcs,   g_srcs);
    cudaGetSymbolAddress(&p_ws,     g_ws);
    cudaGetSymbolAddress(&p_csum,   g_csum);
    cudaGetSymbolAddress(&p_coff,   g_coff);

    const int nch = (N + SCAN_BLOCK - 1) / SCAN_BLOCK;

    // --- CSR build ---
    zero_counts_kernel<<<(N + 255) / 256, 256>>>((int*)p_counts, N);
    hist_kernel<<<(E + 255) / 256, 256>>>(dst, (int*)p_counts, E);
    chunk_sum_kernel<<<nch, SCAN_BLOCK>>>((int*)p_counts, (int*)p_csum, N);
    chunk_scan_kernel<<<1, 128>>>((int*)p_csum, (int*)p_coff, (int*)p_rowoff, nch, N);
    scan_apply_kernel<<<nch, SCAN_BLOCK>>>((int*)p_counts, (int*)p_coff,
                                           (int*)p_rowoff, (int*)p_cursor, N);
    scatter_kernel<<<(E + 255) / 256, 256>>>(src, dst, ew, (int*)p_cursor,
                                             (int*)p_srcs, (float*)p_ws, E);

    // --- layer 1: support1 = feature @ W1 ; x1 = relu(agg + b1) ---
    {
        dim3 grid((H + 127) / 128, (N + 63) / 64);
        sgemm_kernel<64, 128, 16, 8, 4><<<grid, 256>>>(feature, W1, (float*)p_sup1, N, H, F_IN);
    }
    {
        long long threads = (long long)N * 32;
        agg1_kernel<<<(unsigned)((threads + 255) / 256), 256>>>(
            (float*)p_sup1, (int*)p_rowoff, (int*)p_srcs, (float*)p_ws, b1, x1, N);
    }

    // --- layer 2: support2 = x1 @ W2 ; x2 = log_softmax(agg + b2) ---
    {
        dim3 grid((D + 63) / 64, (N + 63) / 64);
        sgemm_kernel<64, 64, 16, 4, 4><<<grid, 256>>>(x1, W2, (float*)p_sup2, N, D, H);
    }
    {
        long long threads = (long long)N * 32;
        agg2_kernel<<<(unsigned)((threads + 255) / 256), 256>>>(
            (float*)p_sup2, (int*)p_rowoff, (int*)p_srcs, (float*)p_ws, b2, x2, N);
    }
}

// round 2
// speedup vs baseline: 1.0128x; 1.0128x over previous
#include <cuda_runtime.h>
#include <math.h>
#include <stdint.h>

// ---------------------------------------------------------------------------
// GCN_77893526880285 on GB300 (sm_103a)
//   layer l: support = X @ Wl ; agg[v] = sum_{e: dst=v} w_e * support[src_e] ; +b
//   x1 = relu(layer1), x2 = log_softmax(layer2)
// R2: GEMMs moved to tensor cores via mma.sync m16n8k8 TF32.
//     CSR-by-dst build (histogram+scan+scatter), atomic-free warp-per-node agg.
// ---------------------------------------------------------------------------

#define NMAX 100352
#define EMAX 1600000
#define HMAX 128
#define DMAX 64
#define NCHUNK_MAX 128
#define SCAN_BLOCK 1024

__device__ float g_support1[(size_t)NMAX * HMAX];   // 51.2 MB
__device__ float g_support2[(size_t)NMAX * DMAX];   // 25.6 MB
__device__ int   g_counts[NMAX];
__device__ int   g_rowoff[NMAX + 1];
__device__ int   g_cursor[NMAX];
__device__ int2  g_edges[EMAX];                     // (src, weight-bits) sorted by dst
__device__ int   g_csum[NCHUNK_MAX];
__device__ int   g_coff[NCHUNK_MAX];

// ---------------------------- CSR build ------------------------------------

__global__ void zero_counts_kernel(int* __restrict__ counts, int N) {
    int i = blockIdx.x * blockDim.x + threadIdx.x;
    if (i < N) counts[i] = 0;
}

__global__ void hist_kernel(const int* __restrict__ dst, int* __restrict__ counts, int E) {
    int i = blockIdx.x * blockDim.x + threadIdx.x;
    if (i < E) atomicAdd(&counts[dst[i]], 1);
}

__global__ void chunk_sum_kernel(const int* __restrict__ counts, int* __restrict__ csum, int N) {
    int i = blockIdx.x * SCAN_BLOCK + threadIdx.x;
    int v = (i < N) ? counts[i] : 0;
    #pragma unroll
    for (int o = 16; o; o >>= 1) v += __shfl_xor_sync(0xffffffffu, v, o);
    __shared__ int ws[32];
    if ((threadIdx.x & 31) == 0) ws[threadIdx.x >> 5] = v;
    __syncthreads();
    if (threadIdx.x < 32) {
        int x = ws[threadIdx.x];
        #pragma unroll
        for (int o = 16; o; o >>= 1) x += __shfl_xor_sync(0xffffffffu, x, o);
        if (threadIdx.x == 0) csum[blockIdx.x] = x;
    }
}

__global__ void chunk_scan_kernel(const int* __restrict__ csum, int* __restrict__ coff,
                                  int* __restrict__ rowoff, int nch, int N) {
    int tid = threadIdx.x;
    int v = (tid < nch) ? csum[tid] : 0;
    int lane = tid & 31, wid = tid >> 5;
    int x = v;
    #pragma unroll
    for (int o = 1; o < 32; o <<= 1) { int t = __shfl_up_sync(0xffffffffu, x, o); if (lane >= o) x += t; }
    __shared__ int ws[4];
    if (lane == 31) ws[wid] = x;
    __syncthreads();
    int base = 0;
    #pragma unroll
    for (int w = 0; w < 4; w++) if (w < wid) base += ws[w];
    int excl = base + x - v;
    if (tid < nch) coff[tid] = excl;
    if (tid == nch - 1) rowoff[N] = excl + v;
}

__global__ void scan_apply_kernel(const int* __restrict__ counts, const int* __restrict__ coff,
                                  int* __restrict__ rowoff, int* __restrict__ cursor, int N) {
    int tid = threadIdx.x, b = blockIdx.x;
    int i = b * SCAN_BLOCK + tid;
    int v = (i < N) ? counts[i] : 0;
    int lane = tid & 31, wid = tid >> 5;
    int x = v;
    #pragma unroll
    for (int o = 1; o < 32; o <<= 1) { int t = __shfl_up_sync(0xffffffffu, x, o); if (lane >= o) x += t; }
    __shared__ int ws[32];
    if (lane == 31) ws[wid] = x;
    __syncthreads();
    if (wid == 0) {
        int y = ws[lane];
        #pragma unroll
        for (int o = 1; o < 32; o <<= 1) { int t = __shfl_up_sync(0xffffffffu, y, o); if (lane >= o) y += t; }
        ws[lane] = y;
    }
    __syncthreads();
    int base = coff[b] + (wid ? ws[wid - 1] : 0);
    int excl = base + x - v;
    if (i < N) { rowoff[i] = excl; cursor[i] = excl; }
}

__global__ void scatter_kernel(const int* __restrict__ src, const int* __restrict__ dst,
                               const float* __restrict__ ew, int* __restrict__ cursor,
                               int2* __restrict__ edges, int E) {
    int i = blockIdx.x * blockDim.x + threadIdx.x;
    if (i < E) {
        int d = dst[i];
        int p = atomicAdd(&cursor[d], 1);
        edges[p] = make_int2(src[i], __float_as_int(ew[i]));
    }
}

// ---------------------------- TF32 tensor GEMM -------------------------------
// C[M, BN] = A[M, K] @ B[K, BN], row-major, BN == full N of the weight matrix.
// Block tile 128 x BN, BK=32, 8 warps. Warp tile 32 x (BN/2).
// smem holds TF32-rounded values with k-permutation within each k8 group:
//   pos(k) = (k%4)*2 + (k/4)  -> fragment pairs (k, k+4) are adjacent -> LDS.64

__device__ __forceinline__ uint32_t f2tf32(float v) {
    uint32_t u;
    asm("cvt.rna.tf32.f32 %0, %1;" : "=r"(u) : "f"(v));
    return u;
}

__device__ __forceinline__ void mma_tf32(float c[4], const uint32_t a[4],
                                         uint32_t b0, uint32_t b1) {
    asm volatile("mma.sync.aligned.m16n8k8.row.col.f32.tf32.tf32.f32 "
                 "{%0,%1,%2,%3}, {%4,%5,%6,%7}, {%8,%9}, {%0,%1,%2,%3};\n"
                 : "+f"(c[0]), "+f"(c[1]), "+f"(c[2]), "+f"(c[3])
                 : "r"(a[0]), "r"(a[1]), "r"(a[2]), "r"(a[3]), "r"(b0), "r"(b1));
}

template<int BN>
__global__ __launch_bounds__(256, 2)
void tf32_gemm_kernel(const float* __restrict__ A, const float* __restrict__ B,
                      float* __restrict__ C, int M, int K) {
    constexpr int BM = 128, BK = 32;
    constexpr int LDSW = 40;                 // 32 + 8 pad -> conflict-free LDS.64
    constexpr int WN = BN / 2;               // warp tile N
    constexpr int NT = WN / 8;               // n-tiles per warp
    __shared__ float As[BM * LDSW];
    __shared__ float Bs[BN * LDSW];

    const int tid = threadIdx.x;
    const int warp = tid >> 5, lane = tid & 31;
    const int wm = warp >> 1;                // 0..3 (M)
    const int wn = warp & 1;                 // 0..1 (N)
    const int lr = lane >> 2;                // 0..7
    const int lc = lane & 3;                 // 0..3
    const int rowBase = blockIdx.x * BM;

    float c[2][NT][4];
    #pragma unroll
    for (int i = 0; i < 2; i++)
        #pragma unroll
        for (int j = 0; j < NT; j++)
            #pragma unroll
            for (int q = 0; q < 4; q++) c[i][j][q] = 0.f;

    for (int k0 = 0; k0 < K; k0 += BK) {
        // --- fill A tile (BM x BK): 1024 float4s, 4 per thread ---
        #pragma unroll
        for (int it = 0; it < 4; it++) {
            int f   = tid + it * 256;
            int row = f >> 3;
            int k4  = f & 7;                    // which float4 in k
            int gr  = rowBase + row;
            float4 v = make_float4(0.f, 0.f, 0.f, 0.f);
            if (gr < M)
                v = *reinterpret_cast<const float4*>(&A[(size_t)gr * K + k0 + k4 * 4]);
            int g   = k4 >> 1;
            int odd = k4 & 1;                   // k%8 >= 4 ?
            float* bp = &As[row * LDSW + g * 8 + odd];
            bp[0] = __uint_as_float(f2tf32(v.x));
            bp[2] = __uint_as_float(f2tf32(v.y));
            bp[4] = __uint_as_float(f2tf32(v.z));
            bp[6] = __uint_as_float(f2tf32(v.w));
        }
        // --- fill B tile (BK x BN) transposed to [n][k_perm] ---
        constexpr int B_ITERS = (BK * BN / 4) / 256;   // 4 (BN=128) or 2 (BN=64)
        #pragma unroll
        for (int it = 0; it < B_ITERS; it++) {
            int f    = tid + it * 256;
            int krow = f / (BN / 4);
            int n0   = (f % (BN / 4)) * 4;
            float4 v = *reinterpret_cast<const float4*>(&B[(size_t)(k0 + krow) * BN + n0]);
            int g  = krow >> 3;
            int cc = krow & 7;
            int p  = ((cc & 3) << 1) | (cc >> 2);
            Bs[(n0 + 0) * LDSW + g * 8 + p] = __uint_as_float(f2tf32(v.x));
            Bs[(n0 + 1) * LDSW + g * 8 + p] = __uint_as_float(f2tf32(v.y));
            Bs[(n0 + 2) * LDSW + g * 8 + p] = __uint_as_float(f2tf32(v.z));
            Bs[(n0 + 3) * LDSW + g * 8 + p] = __uint_as_float(f2tf32(v.w));
        }
        __syncthreads();

        // --- compute: BK/8 = 4 k8-steps ---
        #pragma unroll
        for (int g = 0; g < BK / 8; g++) {
            uint32_t a[2][4];
            #pragma unroll
            for (int mt = 0; mt < 2; mt++) {
                int r0 = wm * 32 + mt * 16 + lr;
                float2 v0 = *reinterpret_cast<const float2*>(&As[r0 * LDSW + g * 8 + 2 * lc]);
                float2 v1 = *reinterpret_cast<const float2*>(&As[(r0 + 8) * LDSW + g * 8 + 2 * lc]);
                a[mt][0] = __float_as_uint(v0.x);
                a[mt][2] = __float_as_uint(v0.y);
                a[mt][1] = __float_as_uint(v1.x);
                a[mt][3] = __float_as_uint(v1.y);
            }
            #pragma unroll
            for (int nt = 0; nt < NT; nt++) {
                int n = wn * WN + nt * 8 + lr;
                float2 bv = *reinterpret_cast<const float2*>(&Bs[n * LDSW + g * 8 + 2 * lc]);
                uint32_t b0 = __float_as_uint(bv.x);
                uint32_t b1 = __float_as_uint(bv.y);
                #pragma unroll
                for (int mt = 0; mt < 2; mt++)
                    mma_tf32(c[mt][nt], a[mt], b0, b1);
            }
        }
        __syncthreads();
    }

    // --- store C ---
    #pragma unroll
    for (int mt = 0; mt < 2; mt++) {
        int r0 = rowBase + wm * 32 + mt * 16 + lr;
        #pragma unroll
        for (int nt = 0; nt < NT; nt++) {
            int col = wn * WN + nt * 8 + 2 * lc;
            if (r0 < M)
                *reinterpret_cast<float2*>(&C[(size_t)r0 * BN + col]) =
                    make_float2(c[mt][nt][0], c[mt][nt][1]);
            if (r0 + 8 < M)
                *reinterpret_cast<float2*>(&C[(size_t)(r0 + 8) * BN + col]) =
                    make_float2(c[mt][nt][2], c[mt][nt][3]);
        }
    }
}

// ------------------------ Aggregation (warp per node) -----------------------

__global__ void agg1_kernel(const float* __restrict__ support, const int* __restrict__ rowoff,
                            const int2* __restrict__ edges,
                            const float* __restrict__ bias, float* __restrict__ out, int N) {
    int gw = (blockIdx.x * blockDim.x + threadIdx.x) >> 5;
    int lane = threadIdx.x & 31;
    if (gw >= N) return;
    int s = rowoff[gw], e = rowoff[gw + 1];
    float4 acc = make_float4(0.f, 0.f, 0.f, 0.f);
    int j = s;
    int2 cur = make_int2(0, 0);
    if (j < e) cur = edges[j];
    while (j < e) {
        int nj = j + 1;
        int2 nxt = make_int2(0, 0);
        if (nj < e) nxt = edges[nj];                         // prefetch next edge
        float cw = __int_as_float(cur.y);
        float4 v = *reinterpret_cast<const float4*>(&support[(size_t)cur.x * 128 + lane * 4]);
        acc.x = fmaf(cw, v.x, acc.x);
        acc.y = fmaf(cw, v.y, acc.y);
        acc.z = fmaf(cw, v.z, acc.z);
        acc.w = fmaf(cw, v.w, acc.w);
        cur = nxt; j = nj;
    }
    float4 bb = *reinterpret_cast<const float4*>(&bias[lane * 4]);
    acc.x = fmaxf(acc.x + bb.x, 0.f);
    acc.y = fmaxf(acc.y + bb.y, 0.f);
    acc.z = fmaxf(acc.z + bb.z, 0.f);
    acc.w = fmaxf(acc.w + bb.w, 0.f);
    *reinterpret_cast<float4*>(&out[(size_t)gw * 128 + lane * 4]) = acc;
}

__global__ void agg2_kernel(const float* __restrict__ support, const int* __restrict__ rowoff,
                            const int2* __restrict__ edges,
                            const float* __restrict__ bias, float* __restrict__ out, int N) {
    int gw = (blockIdx.x * blockDim.x + threadIdx.x) >> 5;
    int lane = threadIdx.x & 31;
    if (gw >= N) return;
    int s = rowoff[gw], e = rowoff[gw + 1];
    float2 acc = make_float2(0.f, 0.f);
    int j = s;
    int2 cur = make_int2(0, 0);
    if (j < e) cur = edges[j];
    while (j < e) {
        int nj = j + 1;
        int2 nxt = make_int2(0, 0);
        if (nj < e) nxt = edges[nj];
        float cw = __int_as_float(cur.y);
        float2 v = *reinterpret_cast<const float2*>(&support[(size_t)cur.x * 64 + lane * 2]);
        acc.x = fmaf(cw, v.x, acc.x);
        acc.y = fmaf(cw, v.y, acc.y);
        cur = nxt; j = nj;
    }
    float2 bb = *reinterpret_cast<const float2*>(&bias[lane * 2]);
    acc.x += bb.x; acc.y += bb.y;
    float m = fmaxf(acc.x, acc.y);
    #pragma unroll
    for (int o = 16; o; o >>= 1) m = fmaxf(m, __shfl_xor_sync(0xffffffffu, m, o));
    float es = expf(acc.x - m) + expf(acc.y - m);
    #pragma unroll
    for (int o = 16; o; o >>= 1) es += __shfl_xor_sync(0xffffffffu, es, o);
    float ls = m + logf(es);
    *reinterpret_cast<float2*>(&out[(size_t)gw * 64 + lane * 2]) =
        make_float2(acc.x - ls, acc.y - ls);
}

// ---------------------------- launch ----------------------------------------

extern "C" void kernel_launch(void* const* d_in, const int* in_sizes, int n_in,
                              void* d_out, int out_size) {
    const float* feature = (const float*)d_in[0];
    const int*   src     = (const int*)d_in[1];
    const int*   dst     = (const int*)d_in[2];
    const float* ew      = (const float*)d_in[3];
    const float* W1      = (const float*)d_in[4];
    const float* b1      = (const float*)d_in[5];
    const float* W2      = (const float*)d_in[6];
    const float* b2      = (const float*)d_in[7];
    float* out = (float*)d_out;

    const int E    = in_sizes[1];
    const int H    = in_sizes[5];            // 128
    const int F_IN = in_sizes[4] / H;        // 256
    const int D    = in_sizes[7];            // 64
    const int N    = in_sizes[0] / F_IN;     // 100000
    (void)H; (void)D;

    float* x1 = out;                          // [N, 128]
    float* x2 = out + (size_t)N * 128;        // [N, 64]

    void *p_sup1, *p_sup2, *p_counts, *p_rowoff, *p_cursor, *p_edges, *p_csum, *p_coff;
    cudaGetSymbolAddress(&p_sup1,   g_support1);
    cudaGetSymbolAddress(&p_sup2,   g_support2);
    cudaGetSymbolAddress(&p_counts, g_counts);
    cudaGetSymbolAddress(&p_rowoff, g_rowoff);
    cudaGetSymbolAddress(&p_cursor, g_cursor);
    cudaGetSymbolAddress(&p_edges,  g_edges);
    cudaGetSymbolAddress(&p_csum,   g_csum);
    cudaGetSymbolAddress(&p_coff,   g_coff);

    const int nch = (N + SCAN_BLOCK - 1) / SCAN_BLOCK;

    // --- CSR build ---
    zero_counts_kernel<<<(N + 255) / 256, 256>>>((int*)p_counts, N);
    hist_kernel<<<(E + 255) / 256, 256>>>(dst, (int*)p_counts, E);
    chunk_sum_kernel<<<nch, SCAN_BLOCK>>>((int*)p_counts, (int*)p_csum, N);
    chunk_scan_kernel<<<1, 128>>>((int*)p_csum, (int*)p_coff, (int*)p_rowoff, nch, N);
    scan_apply_kernel<<<nch, SCAN_BLOCK>>>((int*)p_counts, (int*)p_coff,
                                           (int*)p_rowoff, (int*)p_cursor, N);
    scatter_kernel<<<(E + 255) / 256, 256>>>(src, dst, ew, (int*)p_cursor,
                                             (int2*)p_edges, E);

    // --- layer 1: support1 = feature @ W1 (tf32 TC) ; x1 = relu(agg + b1) ---
    tf32_gemm_kernel<128><<<(N + 127) / 128, 256>>>(feature, W1, (float*)p_sup1, N, F_IN);
    {
        long long threads = (long long)N * 32;
        agg1_kernel<<<(unsigned)((threads + 255) / 256), 256>>>(
            (float*)p_sup1, (int*)p_rowoff, (int2*)p_edges, b1, x1, N);
    }

    // --- layer 2: support2 = x1 @ W2 (tf32 TC) ; x2 = log_softmax(agg + b2) ---
    tf32_gemm_kernel<64><<<(N + 127) / 128, 256>>>(x1, W2, (float*)p_sup2, N, 128);
    {
        long long threads = (long long)N * 32;
        agg2_kernel<<<(unsigned)((threads + 255) / 256), 256>>>(
            (float*)p_sup2, (int*)p_rowoff, (int2*)p_edges, b2, x2, N);
    }
}

// round 3
// speedup vs baseline: 1.1696x; 1.1549x over previous
#include <cuda_runtime.h>
#include <math.h>
#include <stdint.h>

// ---------------------------------------------------------------------------
// GCN_77893526880285 on GB300 (sm_103a)
// R3: cp.async double-buffered TF32 tensor GEMM; 4x-unrolled atomic-free
//     warp-per-node aggregation; CSR build overlapped with GEMM1 on a side
//     stream (fork/join graph capture pattern).
// ---------------------------------------------------------------------------

#define NMAX 100352
#define EMAX 1600000
#define NCHUNK_MAX 128
#define SCAN_BLOCK 1024

__device__ float g_support1[(size_t)NMAX * 128];   // 51.2 MB
__device__ float g_support2[(size_t)NMAX * 64];    // 25.6 MB
__device__ int   g_counts[NMAX];
__device__ int   g_rowoff[NMAX + 1];
__device__ int   g_cursor[NMAX];
__device__ int2  g_edges[EMAX];                    // (src, weight-bits) sorted by dst
__device__ int   g_csum[NCHUNK_MAX];
__device__ int   g_coff[NCHUNK_MAX];

// ---------------------------- CSR build ------------------------------------

__global__ void zero_counts_kernel(int* __restrict__ counts, int N) {
    int i = blockIdx.x * blockDim.x + threadIdx.x;
    if (i < N) counts[i] = 0;
}

__global__ void hist_kernel(const int* __restrict__ dst, int* __restrict__ counts, int E) {
    int i = blockIdx.x * blockDim.x + threadIdx.x;
    if (i < E) atomicAdd(&counts[dst[i]], 1);
}

__global__ void chunk_sum_kernel(const int* __restrict__ counts, int* __restrict__ csum, int N) {
    int i = blockIdx.x * SCAN_BLOCK + threadIdx.x;
    int v = (i < N) ? counts[i] : 0;
    #pragma unroll
    for (int o = 16; o; o >>= 1) v += __shfl_xor_sync(0xffffffffu, v, o);
    __shared__ int ws[32];
    if ((threadIdx.x & 31) == 0) ws[threadIdx.x >> 5] = v;
    __syncthreads();
    if (threadIdx.x < 32) {
        int x = ws[threadIdx.x];
        #pragma unroll
        for (int o = 16; o; o >>= 1) x += __shfl_xor_sync(0xffffffffu, x, o);
        if (threadIdx.x == 0) csum[blockIdx.x] = x;
    }
}

__global__ void chunk_scan_kernel(const int* __restrict__ csum, int* __restrict__ coff,
                                  int* __restrict__ rowoff, int nch, int N) {
    int tid = threadIdx.x;
    int v = (tid < nch) ? csum[tid] : 0;
    int lane = tid & 31, wid = tid >> 5;
    int x = v;
    #pragma unroll
    for (int o = 1; o < 32; o <<= 1) { int t = __shfl_up_sync(0xffffffffu, x, o); if (lane >= o) x += t; }
    __shared__ int ws[4];
    if (lane == 31) ws[wid] = x;
    __syncthreads();
    int base = 0;
    #pragma unroll
    for (int w = 0; w < 4; w++) if (w < wid) base += ws[w];
    int excl = base + x - v;
    if (tid < nch) coff[tid] = excl;
    if (tid == nch - 1) rowoff[N] = excl + v;
}

__global__ void scan_apply_kernel(const int* __restrict__ counts, const int* __restrict__ coff,
                                  int* __restrict__ rowoff, int* __restrict__ cursor, int N) {
    int tid = threadIdx.x, b = blockIdx.x;
    int i = b * SCAN_BLOCK + tid;
    int v = (i < N) ? counts[i] : 0;
    int lane = tid & 31, wid = tid >> 5;
    int x = v;
    #pragma unroll
    for (int o = 1; o < 32; o <<= 1) { int t = __shfl_up_sync(0xffffffffu, x, o); if (lane >= o) x += t; }
    __shared__ int ws[32];
    if (lane == 31) ws[wid] = x;
    __syncthreads();
    if (wid == 0) {
        int y = ws[lane];
        #pragma unroll
        for (int o = 1; o < 32; o <<= 1) { int t = __shfl_up_sync(0xffffffffu, y, o); if (lane >= o) y += t; }
        ws[lane] = y;
    }
    __syncthreads();
    int base = coff[b] + (wid ? ws[wid - 1] : 0);
    int excl = base + x - v;
    if (i < N) { rowoff[i] = excl; cursor[i] = excl; }
}

__global__ void scatter_kernel(const int* __restrict__ src, const int* __restrict__ dst,
                               const float* __restrict__ ew, int* __restrict__ cursor,
                               int2* __restrict__ edges, int E) {
    int i = blockIdx.x * blockDim.x + threadIdx.x;
    if (i < E) {
        int d = dst[i];
        int p = atomicAdd(&cursor[d], 1);
        edges[p] = make_int2(src[i], __float_as_int(ew[i]));
    }
}

// ---------------------- TF32 GEMM, cp.async double-buffered ------------------
// C[M, BN] = A[M, K] @ B[K, BN], row-major. Block 128 x BN, BK=32, 8 warps.
// Raw fp32 in smem (natural layout, padded), tf32 cvt in registers.

__device__ __forceinline__ uint32_t f2tf32(float v) {
    uint32_t u;
    asm("cvt.rna.tf32.f32 %0, %1;" : "=r"(u) : "f"(v));
    return u;
}

__device__ __forceinline__ void cp16(float* dst_smem, const float* src, int srcsz) {
    uint32_t d = (uint32_t)__cvta_generic_to_shared(dst_smem);
    asm volatile("cp.async.cg.shared.global [%0], [%1], 16, %2;\n"
                 :: "r"(d), "l"(src), "r"(srcsz));
}

__device__ __forceinline__ void mma_tf32(float c[4], const uint32_t a[4],
                                         uint32_t b0, uint32_t b1) {
    asm volatile("mma.sync.aligned.m16n8k8.row.col.f32.tf32.tf32.f32 "
                 "{%0,%1,%2,%3}, {%4,%5,%6,%7}, {%8,%9}, {%0,%1,%2,%3};\n"
                 : "+f"(c[0]), "+f"(c[1]), "+f"(c[2]), "+f"(c[3])
                 : "r"(a[0]), "r"(a[1]), "r"(a[2]), "r"(a[3]), "r"(b0), "r"(b1));
}

template<int BN>
__global__ __launch_bounds__(256, 2)
void tf32_gemm_kernel(const float* __restrict__ A, const float* __restrict__ B,
                      float* __restrict__ C, int M, int K) {
    constexpr int BM = 128, BK = 32;
    constexpr int ALD = 36;                  // A smem row pitch (floats)
    constexpr int BLD = BN + 8;              // B smem row pitch (floats)
    constexpr int ASTG = BM * ALD;
    constexpr int BSTG = BK * BLD;
    constexpr int WN = BN / 2;
    constexpr int NT = WN / 8;
    extern __shared__ float sm[];
    float* As = sm;                           // [2][BM][ALD]
    float* Bs = sm + 2 * ASTG;                // [2][BK][BLD]

    const int tid = threadIdx.x;
    const int warp = tid >> 5, lane = tid & 31;
    const int wm = warp >> 1, wn = warp & 1;
    const int lr = lane >> 2, lc = lane & 3;
    const int rowBase = blockIdx.x * BM;

    float c[2][NT][4];
    #pragma unroll
    for (int i = 0; i < 2; i++)
        #pragma unroll
        for (int j = 0; j < NT; j++)
            #pragma unroll
            for (int q = 0; q < 4; q++) c[i][j][q] = 0.f;

    const int ktiles = K / BK;

    auto fillA = [&](int t, int stg) {
        int k0 = t * BK;
        #pragma unroll
        for (int it = 0; it < 4; it++) {                 // 1024 16B chunks
            int f = tid + it * 256;
            int row = f >> 3, k4 = f & 7;
            int gr = rowBase + row;
            const float* src = A + (size_t)(gr < M ? gr : 0) * K + k0 + k4 * 4;
            cp16(As + stg * ASTG + row * ALD + k4 * 4, src, gr < M ? 16 : 0);
        }
    };
    auto fillB = [&](int t, int stg) {
        int k0 = t * BK;
        constexpr int BCH = (BK * BN / 4) / 256;         // 4 (BN=128) / 2 (BN=64)
        #pragma unroll
        for (int it = 0; it < BCH; it++) {
            int f = tid + it * 256;
            int krow = f / (BN / 4), nc = f % (BN / 4);
            cp16(Bs + stg * BSTG + krow * BLD + nc * 4,
                 B + (size_t)(k0 + krow) * BN + nc * 4, 16);
        }
    };

    fillA(0, 0); fillB(0, 0);
    asm volatile("cp.async.commit_group;\n");

    for (int t = 0; t < ktiles; t++) {
        int cur = t & 1;
        if (t + 1 < ktiles) {
            fillA(t + 1, cur ^ 1); fillB(t + 1, cur ^ 1);
            asm volatile("cp.async.commit_group;\n");
            asm volatile("cp.async.wait_group 1;\n");
        } else {
            asm volatile("cp.async.wait_group 0;\n");
        }
        __syncthreads();

        const float* Ab = As + cur * ASTG;
        const float* Bb = Bs + cur * BSTG;
        #pragma unroll
        for (int g = 0; g < BK / 8; g++) {
            uint32_t a[2][4];
            #pragma unroll
            for (int mt = 0; mt < 2; mt++) {
                const float* ap = Ab + (wm * 32 + mt * 16 + lr) * ALD + g * 8 + lc;
                a[mt][0] = f2tf32(ap[0]);
                a[mt][2] = f2tf32(ap[4]);
                a[mt][1] = f2tf32(ap[8 * ALD]);
                a[mt][3] = f2tf32(ap[8 * ALD + 4]);
            }
            #pragma unroll
            for (int nt = 0; nt < NT; nt++) {
                const float* bp = Bb + (g * 8 + lc) * BLD + wn * WN + nt * 8 + lr;
                uint32_t b0 = f2tf32(bp[0]);
                uint32_t b1 = f2tf32(bp[4 * BLD]);
                #pragma unroll
                for (int mt = 0; mt < 2; mt++)
                    mma_tf32(c[mt][nt], a[mt], b0, b1);
            }
        }
        __syncthreads();
    }

    #pragma unroll
    for (int mt = 0; mt < 2; mt++) {
        int r0 = rowBase + wm * 32 + mt * 16 + lr;
        #pragma unroll
        for (int nt = 0; nt < NT; nt++) {
            int col = wn * WN + nt * 8 + 2 * lc;
            if (r0 < M)
                *reinterpret_cast<float2*>(&C[(size_t)r0 * BN + col]) =
                    make_float2(c[mt][nt][0], c[mt][nt][1]);
            if (r0 + 8 < M)
                *reinterpret_cast<float2*>(&C[(size_t)(r0 + 8) * BN + col]) =
                    make_float2(c[mt][nt][2], c[mt][nt][3]);
        }
    }
}

// ------------------- Aggregation (warp per node, 4x unrolled) ----------------

__global__ void agg1_kernel(const float* __restrict__ support, const int* __restrict__ rowoff,
                            const int2* __restrict__ edges,
                            const float* __restrict__ bias, float* __restrict__ out, int N) {
    int gw = (blockIdx.x * blockDim.x + threadIdx.x) >> 5;
    int lane = threadIdx.x & 31;
    if (gw >= N) return;
    int s = rowoff[gw], e = rowoff[gw + 1];
    float4 acc0 = make_float4(0.f, 0.f, 0.f, 0.f);
    float4 acc1 = make_float4(0.f, 0.f, 0.f, 0.f);
    int j = s;
    for (; j + 4 <= e; j += 4) {
        int2 e0 = edges[j], e1 = edges[j + 1], e2 = edges[j + 2], e3 = edges[j + 3];
        const float4* p0 = reinterpret_cast<const float4*>(&support[(size_t)e0.x * 128]) + lane;
        const float4* p1 = reinterpret_cast<const float4*>(&support[(size_t)e1.x * 128]) + lane;
        const float4* p2 = reinterpret_cast<const float4*>(&support[(size_t)e2.x * 128]) + lane;
        const float4* p3 = reinterpret_cast<const float4*>(&support[(size_t)e3.x * 128]) + lane;
        float4 v0 = *p0, v1 = *p1, v2 = *p2, v3 = *p3;
        float w0 = __int_as_float(e0.y), w1 = __int_as_float(e1.y);
        float w2 = __int_as_float(e2.y), w3 = __int_as_float(e3.y);
        acc0.x = fmaf(w0, v0.x, acc0.x); acc0.y = fmaf(w0, v0.y, acc0.y);
        acc0.z = fmaf(w0, v0.z, acc0.z); acc0.w = fmaf(w0, v0.w, acc0.w);
        acc1.x = fmaf(w1, v1.x, acc1.x); acc1.y = fmaf(w1, v1.y, acc1.y);
        acc1.z = fmaf(w1, v1.z, acc1.z); acc1.w = fmaf(w1, v1.w, acc1.w);
        acc0.x = fmaf(w2, v2.x, acc0.x); acc0.y = fmaf(w2, v2.y, acc0.y);
        acc0.z = fmaf(w2, v2.z, acc0.z); acc0.w = fmaf(w2, v2.w, acc0.w);
        acc1.x = fmaf(w3, v3.x, acc1.x); acc1.y = fmaf(w3, v3.y, acc1.y);
        acc1.z = fmaf(w3, v3.z, acc1.z); acc1.w = fmaf(w3, v3.w, acc1.w);
    }
    for (; j < e; j++) {
        int2 ee = edges[j];
        float w = __int_as_float(ee.y);
        float4 v = *(reinterpret_cast<const float4*>(&support[(size_t)ee.x * 128]) + lane);
        acc0.x = fmaf(w, v.x, acc0.x); acc0.y = fmaf(w, v.y, acc0.y);
        acc0.z = fmaf(w, v.z, acc0.z); acc0.w = fmaf(w, v.w, acc0.w);
    }
    float4 bb = *(reinterpret_cast<const float4*>(bias) + lane);
    float4 r;
    r.x = fmaxf(acc0.x + acc1.x + bb.x, 0.f);
    r.y = fmaxf(acc0.y + acc1.y + bb.y, 0.f);
    r.z = fmaxf(acc0.z + acc1.z + bb.z, 0.f);
    r.w = fmaxf(acc0.w + acc1.w + bb.w, 0.f);
    *(reinterpret_cast<float4*>(&out[(size_t)gw * 128]) + lane) = r;
}

__global__ void agg2_kernel(const float* __restrict__ support, const int* __restrict__ rowoff,
                            const int2* __restrict__ edges,
                            const float* __restrict__ bias, float* __restrict__ out, int N) {
    int gw = (blockIdx.x * blockDim.x + threadIdx.x) >> 5;
    int lane = threadIdx.x & 31;
    if (gw >= N) return;
    int s = rowoff[gw], e = rowoff[gw + 1];
    float2 acc0 = make_float2(0.f, 0.f), acc1 = make_float2(0.f, 0.f);
    int j = s;
    for (; j + 4 <= e; j += 4) {
        int2 e0 = edges[j], e1 = edges[j + 1], e2 = edges[j + 2], e3 = edges[j + 3];
        float2 v0 = *(reinterpret_cast<const float2*>(&support[(size_t)e0.x * 64]) + lane);
        float2 v1 = *(reinterpret_cast<const float2*>(&support[(size_t)e1.x * 64]) + lane);
        float2 v2 = *(reinterpret_cast<const float2*>(&support[(size_t)e2.x * 64]) + lane);
        float2 v3 = *(reinterpret_cast<const float2*>(&support[(size_t)e3.x * 64]) + lane);
        float w0 = __int_as_float(e0.y), w1 = __int_as_float(e1.y);
        float w2 = __int_as_float(e2.y), w3 = __int_as_float(e3.y);
        acc0.x = fmaf(w0, v0.x, acc0.x); acc0.y = fmaf(w0, v0.y, acc0.y);
        acc1.x = fmaf(w1, v1.x, acc1.x); acc1.y = fmaf(w1, v1.y, acc1.y);
        acc0.x = fmaf(w2, v2.x, acc0.x); acc0.y = fmaf(w2, v2.y, acc0.y);
        acc1.x = fmaf(w3, v3.x, acc1.x); acc1.y = fmaf(w3, v3.y, acc1.y);
    }
    for (; j < e; j++) {
        int2 ee = edges[j];
        float w = __int_as_float(ee.y);
        float2 v = *(reinterpret_cast<const float2*>(&support[(size_t)ee.x * 64]) + lane);
        acc0.x = fmaf(w, v.x, acc0.x); acc0.y = fmaf(w, v.y, acc0.y);
    }
    float2 bb = *(reinterpret_cast<const float2*>(bias) + lane);
    float ax = acc0.x + acc1.x + bb.x;
    float ay = acc0.y + acc1.y + bb.y;
    float m = fmaxf(ax, ay);
    #pragma unroll
    for (int o = 16; o; o >>= 1) m = fmaxf(m, __shfl_xor_sync(0xffffffffu, m, o));
    float es = expf(ax - m) + expf(ay - m);
    #pragma unroll
    for (int o = 16; o; o >>= 1) es += __shfl_xor_sync(0xffffffffu, es, o);
    float ls = m + logf(es);
    *(reinterpret_cast<float2*>(&out[(size_t)gw * 64]) + lane) = make_float2(ax - ls, ay - ls);
}

// ---------------------------- launch ----------------------------------------

extern "C" void kernel_launch(void* const* d_in, const int* in_sizes, int n_in,
                              void* d_out, int out_size) {
    const float* feature = (const float*)d_in[0];
    const int*   src     = (const int*)d_in[1];
    const int*   dst     = (const int*)d_in[2];
    const float* ew      = (const float*)d_in[3];
    const float* W1      = (const float*)d_in[4];
    const float* b1      = (const float*)d_in[5];
    const float* W2      = (const float*)d_in[6];
    const float* b2      = (const float*)d_in[7];
    float* out = (float*)d_out;

    const int E    = in_sizes[1];
    const int H    = in_sizes[5];            // 128
    const int F_IN = in_sizes[4] / H;        // 256
    const int N    = in_sizes[0] / F_IN;     // 100000

    float* x1 = out;                          // [N, 128]
    float* x2 = out + (size_t)N * 128;        // [N, 64]

    void *p_sup1, *p_sup2, *p_counts, *p_rowoff, *p_cursor, *p_edges, *p_csum, *p_coff;
    cudaGetSymbolAddress(&p_sup1,   g_support1);
    cudaGetSymbolAddress(&p_sup2,   g_support2);
    cudaGetSymbolAddress(&p_counts, g_counts);
    cudaGetSymbolAddress(&p_rowoff, g_rowoff);
    cudaGetSymbolAddress(&p_cursor, g_cursor);
    cudaGetSymbolAddress(&p_edges,  g_edges);
    cudaGetSymbolAddress(&p_csum,   g_csum);
    cudaGetSymbolAddress(&p_coff,   g_coff);

    constexpr int SMEM1 = (2 * 128 * 36 + 2 * 32 * 136) * 4;   // 71680 B
    constexpr int SMEM2 = (2 * 128 * 36 + 2 * 32 * 72) * 4;    // 55296 B
    cudaFuncSetAttribute(tf32_gemm_kernel<128>,
                         cudaFuncAttributeMaxDynamicSharedMemorySize, SMEM1);
    cudaFuncSetAttribute(tf32_gemm_kernel<64>,
                         cudaFuncAttributeMaxDynamicSharedMemorySize, SMEM2);

    // Lazily created side stream + events (first call is the uncaptured
    // correctness run; creation happens outside graph capture).
    static cudaStream_t s_side = nullptr;
    static cudaEvent_t ev_fork = nullptr, ev_join = nullptr;
    if (s_side == nullptr) {
        cudaStreamCreateWithFlags(&s_side, cudaStreamNonBlocking);
        cudaEventCreateWithFlags(&ev_fork, cudaEventDisableTiming);
        cudaEventCreateWithFlags(&ev_join, cudaEventDisableTiming);
    }

    const int nch = (N + SCAN_BLOCK - 1) / SCAN_BLOCK;

    // fork: CSR build on side stream, GEMM1 on main stream
    cudaEventRecord(ev_fork, 0);
    cudaStreamWaitEvent(s_side, ev_fork, 0);

    zero_counts_kernel<<<(N + 255) / 256, 256, 0, s_side>>>((int*)p_counts, N);
    hist_kernel<<<(E + 255) / 256, 256, 0, s_side>>>(dst, (int*)p_counts, E);
    chunk_sum_kernel<<<nch, SCAN_BLOCK, 0, s_side>>>((int*)p_counts, (int*)p_csum, N);
    chunk_scan_kernel<<<1, 128, 0, s_side>>>((int*)p_csum, (int*)p_coff, (int*)p_rowoff, nch, N);
    scan_apply_kernel<<<nch, SCAN_BLOCK, 0, s_side>>>((int*)p_counts, (int*)p_coff,
                                                      (int*)p_rowoff, (int*)p_cursor, N);
    scatter_kernel<<<(E + 255) / 256, 256, 0, s_side>>>(src, dst, ew, (int*)p_cursor,
                                                        (int2*)p_edges, E);

    tf32_gemm_kernel<128><<<(N + 127) / 128, 256, SMEM1>>>(feature, W1, (float*)p_sup1, N, F_IN);

    // join
    cudaEventRecord(ev_join, s_side);
    cudaStreamWaitEvent(0, ev_join, 0);

    {
        long long threads = (long long)N * 32;
        agg1_kernel<<<(unsigned)((threads + 255) / 256), 256>>>(
            (float*)p_sup1, (int*)p_rowoff, (int2*)p_edges, b1, x1, N);
    }

    tf32_gemm_kernel<64><<<(N + 127) / 128, 256, SMEM2>>>(x1, W2, (float*)p_sup2, N, 128);

    {
        long long threads = (long long)N * 32;
        agg2_kernel<<<(unsigned)((threads + 255) / 256), 256>>>(
            (float*)p_sup2, (int*)p_rowoff, (int2*)p_edges, b2, x2, N);
    }
}

// round 4
// speedup vs baseline: 1.7349x; 1.4833x over previous
#include <cuda_runtime.h>
#include <math.h>
#include <stdint.h>

// ---------------------------------------------------------------------------
// GCN_77893526880285 on GB300 (sm_103a)
// R4: 3-stage cp.async TF32 GEMM with zero in-loop cvt (weights pre-rounded
//     to tf32; activations truncated by HW), 8x-unrolled aggregation,
//     CSR build overlapped with GEMM1.
// ---------------------------------------------------------------------------

#define NMAX 100352
#define EMAX 1600000
#define NCHUNK_MAX 128
#define SCAN_BLOCK 1024

__device__ float g_support1[(size_t)NMAX * 128];   // 51.2 MB
__device__ float g_support2[(size_t)NMAX * 64];    // 25.6 MB
__device__ float g_W1r[256 * 128];
__device__ float g_W2r[128 * 64];
__device__ int   g_counts[NMAX];
__device__ int   g_rowoff[NMAX + 1];
__device__ int   g_cursor[NMAX];
__device__ int2  g_edges[EMAX];
__device__ int   g_csum[NCHUNK_MAX];
__device__ int   g_coff[NCHUNK_MAX];

// ---------------------------- small helpers ---------------------------------

__device__ __forceinline__ uint32_t f2tf32(float v) {
    uint32_t u;
    asm("cvt.rna.tf32.f32 %0, %1;" : "=r"(u) : "f"(v));
    return u;
}

__global__ void round_weights_kernel(const float* __restrict__ W1, const float* __restrict__ W2,
                                     float* __restrict__ W1r, float* __restrict__ W2r,
                                     int n1, int n2) {
    int i = blockIdx.x * blockDim.x + threadIdx.x;
    if (i < n1) W1r[i] = __uint_as_float(f2tf32(W1[i]));
    else if (i < n1 + n2) W2r[i - n1] = __uint_as_float(f2tf32(W2[i - n1]));
}

// ---------------------------- CSR build ------------------------------------

__global__ void zero_counts_kernel(int* __restrict__ counts, int N) {
    int i = blockIdx.x * blockDim.x + threadIdx.x;
    if (i < N) counts[i] = 0;
}

__global__ void hist_kernel(const int* __restrict__ dst, int* __restrict__ counts, int E) {
    int i = blockIdx.x * blockDim.x + threadIdx.x;
    if (i < E) atomicAdd(&counts[dst[i]], 1);
}

__global__ void chunk_sum_kernel(const int* __restrict__ counts, int* __restrict__ csum, int N) {
    int i = blockIdx.x * SCAN_BLOCK + threadIdx.x;
    int v = (i < N) ? counts[i] : 0;
    #pragma unroll
    for (int o = 16; o; o >>= 1) v += __shfl_xor_sync(0xffffffffu, v, o);
    __shared__ int ws[32];
    if ((threadIdx.x & 31) == 0) ws[threadIdx.x >> 5] = v;
    __syncthreads();
    if (threadIdx.x < 32) {
        int x = ws[threadIdx.x];
        #pragma unroll
        for (int o = 16; o; o >>= 1) x += __shfl_xor_sync(0xffffffffu, x, o);
        if (threadIdx.x == 0) csum[blockIdx.x] = x;
    }
}

__global__ void chunk_scan_kernel(const int* __restrict__ csum, int* __restrict__ coff,
                                  int* __restrict__ rowoff, int nch, int N) {
    int tid = threadIdx.x;
    int v = (tid < nch) ? csum[tid] : 0;
    int lane = tid & 31, wid = tid >> 5;
    int x = v;
    #pragma unroll
    for (int o = 1; o < 32; o <<= 1) { int t = __shfl_up_sync(0xffffffffu, x, o); if (lane >= o) x += t; }
    __shared__ int ws[4];
    if (lane == 31) ws[wid] = x;
    __syncthreads();
    int base = 0;
    #pragma unroll
    for (int w = 0; w < 4; w++) if (w < wid) base += ws[w];
    int excl = base + x - v;
    if (tid < nch) coff[tid] = excl;
    if (tid == nch - 1) rowoff[N] = excl + v;
}

__global__ void scan_apply_kernel(const int* __restrict__ counts, const int* __restrict__ coff,
                                  int* __restrict__ rowoff, int* __restrict__ cursor, int N) {
    int tid = threadIdx.x, b = blockIdx.x;
    int i = b * SCAN_BLOCK + tid;
    int v = (i < N) ? counts[i] : 0;
    int lane = tid & 31, wid = tid >> 5;
    int x = v;
    #pragma unroll
    for (int o = 1; o < 32; o <<= 1) { int t = __shfl_up_sync(0xffffffffu, x, o); if (lane >= o) x += t; }
    __shared__ int ws[32];
    if (lane == 31) ws[wid] = x;
    __syncthreads();
    if (wid == 0) {
        int y = ws[lane];
        #pragma unroll
        for (int o = 1; o < 32; o <<= 1) { int t = __shfl_up_sync(0xffffffffu, y, o); if (lane >= o) y += t; }
        ws[lane] = y;
    }
    __syncthreads();
    int base = coff[b] + (wid ? ws[wid - 1] : 0);
    int excl = base + x - v;
    if (i < N) { rowoff[i] = excl; cursor[i] = excl; }
}

__global__ void scatter_kernel(const int* __restrict__ src, const int* __restrict__ dst,
                               const float* __restrict__ ew, int* __restrict__ cursor,
                               int2* __restrict__ edges, int E) {
    int i = blockIdx.x * blockDim.x + threadIdx.x;
    if (i < E) {
        int d = dst[i];
        int p = atomicAdd(&cursor[d], 1);
        edges[p] = make_int2(src[i], __float_as_int(ew[i]));
    }
}

// ---------------- TF32 GEMM, 3-stage cp.async, no in-loop cvt ----------------
// C[M,BN] = A[M,K] @ B[K,BN].  B must be pre-rounded to tf32 values.
// A is fed as raw fp32 bits (HW uses the top 19 bits).

__device__ __forceinline__ void cp16(float* dst_smem, const float* src, int srcsz) {
    uint32_t d = (uint32_t)__cvta_generic_to_shared(dst_smem);
    asm volatile("cp.async.cg.shared.global [%0], [%1], 16, %2;\n"
                 :: "r"(d), "l"(src), "r"(srcsz));
}

__device__ __forceinline__ void mma_tf32(float c[4], const uint32_t a[4],
                                         uint32_t b0, uint32_t b1) {
    asm volatile("mma.sync.aligned.m16n8k8.row.col.f32.tf32.tf32.f32 "
                 "{%0,%1,%2,%3}, {%4,%5,%6,%7}, {%8,%9}, {%0,%1,%2,%3};\n"
                 : "+f"(c[0]), "+f"(c[1]), "+f"(c[2]), "+f"(c[3])
                 : "r"(a[0]), "r"(a[1]), "r"(a[2]), "r"(a[3]), "r"(b0), "r"(b1));
}

template<int BN>
__global__ __launch_bounds__(256, 2)
void tf32_gemm_kernel(const float* __restrict__ A, const float* __restrict__ B,
                      float* __restrict__ C, int M, int K) {
    constexpr int BM = 128, BK = 32, S = 3;
    constexpr int ALD = 36;
    constexpr int BLD = BN + 8;
    constexpr int ASTG = BM * ALD;
    constexpr int BSTG = BK * BLD;
    constexpr int WN = BN / 2;
    constexpr int NT = WN / 8;
    extern __shared__ float sm[];
    float* As = sm;                   // [S][BM][ALD]
    float* Bs = sm + S * ASTG;        // [S][BK][BLD]

    const int tid = threadIdx.x;
    const int warp = tid >> 5, lane = tid & 31;
    const int wm = warp >> 1, wn = warp & 1;
    const int lr = lane >> 2, lc = lane & 3;
    const int rowBase = blockIdx.x * BM;

    float c[2][NT][4];
    #pragma unroll
    for (int i = 0; i < 2; i++)
        #pragma unroll
        for (int j = 0; j < NT; j++)
            #pragma unroll
            for (int q = 0; q < 4; q++) c[i][j][q] = 0.f;

    const int ktiles = K / BK;

    auto fill = [&](int t, int stg) {
        int k0 = t * BK;
        #pragma unroll
        for (int it = 0; it < 4; it++) {
            int f = tid + it * 256;
            int row = f >> 3, k4 = f & 7;
            int gr = rowBase + row;
            const float* srcp = A + (size_t)(gr < M ? gr : 0) * K + k0 + k4 * 4;
            cp16(As + stg * ASTG + row * ALD + k4 * 4, srcp, gr < M ? 16 : 0);
        }
        constexpr int BCH = (BK * BN / 4) / 256;
        #pragma unroll
        for (int it = 0; it < BCH; it++) {
            int f = tid + it * 256;
            int krow = f / (BN / 4), nc = f % (BN / 4);
            cp16(Bs + stg * BSTG + krow * BLD + nc * 4,
                 B + (size_t)(k0 + krow) * BN + nc * 4, 16);
        }
        asm volatile("cp.async.commit_group;\n");
    };

    fill(0, 0);
    if (1 < ktiles) fill(1, 1);

    for (int t = 0; t < ktiles; t++) {
        if (t < ktiles - 1) asm volatile("cp.async.wait_group 1;\n");
        else                asm volatile("cp.async.wait_group 0;\n");
        __syncthreads();
        if (t + 2 < ktiles) fill(t + 2, (t + 2) % S);

        const float* Ab = As + (t % S) * ASTG;
        const float* Bb = Bs + (t % S) * BSTG;
        #pragma unroll
        for (int g = 0; g < BK / 8; g++) {
            uint32_t a[2][4];
            #pragma unroll
            for (int mt = 0; mt < 2; mt++) {
                const float* ap = Ab + (wm * 32 + mt * 16 + lr) * ALD + g * 8 + lc;
                a[mt][0] = __float_as_uint(ap[0]);
                a[mt][2] = __float_as_uint(ap[4]);
                a[mt][1] = __float_as_uint(ap[8 * ALD]);
                a[mt][3] = __float_as_uint(ap[8 * ALD + 4]);
            }
            #pragma unroll
            for (int nt = 0; nt < NT; nt++) {
                const float* bp = Bb + (g * 8 + lc) * BLD + wn * WN + nt * 8 + lr;
                uint32_t b0 = __float_as_uint(bp[0]);
                uint32_t b1 = __float_as_uint(bp[4 * BLD]);
                #pragma unroll
                for (int mt = 0; mt < 2; mt++)
                    mma_tf32(c[mt][nt], a[mt], b0, b1);
            }
        }
        __syncthreads();   // protect slot reuse ordering across warps
    }

    #pragma unroll
    for (int mt = 0; mt < 2; mt++) {
        int r0 = rowBase + wm * 32 + mt * 16 + lr;
        #pragma unroll
        for (int nt = 0; nt < NT; nt++) {
            int col = wn * WN + nt * 8 + 2 * lc;
            if (r0 < M)
                *reinterpret_cast<float2*>(&C[(size_t)r0 * BN + col]) =
                    make_float2(c[mt][nt][0], c[mt][nt][1]);
            if (r0 + 8 < M)
                *reinterpret_cast<float2*>(&C[(size_t)(r0 + 8) * BN + col]) =
                    make_float2(c[mt][nt][2], c[mt][nt][3]);
        }
    }
}

// ------------------- Aggregation (warp per node, 8x unrolled) ----------------

__global__ __launch_bounds__(128)
void agg1_kernel(const float* __restrict__ support, const int* __restrict__ rowoff,
                 const int2* __restrict__ edges,
                 const float* __restrict__ bias, float* __restrict__ out, int N) {
    int gw = (blockIdx.x * blockDim.x + threadIdx.x) >> 5;
    int lane = threadIdx.x & 31;
    if (gw >= N) return;
    int s = rowoff[gw], e = rowoff[gw + 1];
    float4 acc0 = make_float4(0.f, 0.f, 0.f, 0.f);
    float4 acc1 = make_float4(0.f, 0.f, 0.f, 0.f);
    int j = s;
    for (; j + 8 <= e; j += 8) {
        int2 ee[8];
        #pragma unroll
        for (int q = 0; q < 8; q++) ee[q] = __ldg(&edges[j + q]);
        float4 v[8];
        #pragma unroll
        for (int q = 0; q < 8; q++)
            v[q] = *(reinterpret_cast<const float4*>(&support[(size_t)ee[q].x * 128]) + lane);
        #pragma unroll
        for (int q = 0; q < 8; q++) {
            float w = __int_as_float(ee[q].y);
            float4* ac = (q & 1) ? &acc1 : &acc0;
            ac->x = fmaf(w, v[q].x, ac->x); ac->y = fmaf(w, v[q].y, ac->y);
            ac->z = fmaf(w, v[q].z, ac->z); ac->w = fmaf(w, v[q].w, ac->w);
        }
    }
    for (; j + 2 <= e; j += 2) {
        int2 e0 = __ldg(&edges[j]), e1 = __ldg(&edges[j + 1]);
        float4 v0 = *(reinterpret_cast<const float4*>(&support[(size_t)e0.x * 128]) + lane);
        float4 v1 = *(reinterpret_cast<const float4*>(&support[(size_t)e1.x * 128]) + lane);
        float w0 = __int_as_float(e0.y), w1 = __int_as_float(e1.y);
        acc0.x = fmaf(w0, v0.x, acc0.x); acc0.y = fmaf(w0, v0.y, acc0.y);
        acc0.z = fmaf(w0, v0.z, acc0.z); acc0.w = fmaf(w0, v0.w, acc0.w);
        acc1.x = fmaf(w1, v1.x, acc1.x); acc1.y = fmaf(w1, v1.y, acc1.y);
        acc1.z = fmaf(w1, v1.z, acc1.z); acc1.w = fmaf(w1, v1.w, acc1.w);
    }
    if (j < e) {
        int2 e0 = __ldg(&edges[j]);
        float w = __int_as_float(e0.y);
        float4 v = *(reinterpret_cast<const float4*>(&support[(size_t)e0.x * 128]) + lane);
        acc0.x = fmaf(w, v.x, acc0.x); acc0.y = fmaf(w, v.y, acc0.y);
        acc0.z = fmaf(w, v.z, acc0.z); acc0.w = fmaf(w, v.w, acc0.w);
    }
    float4 bb = *(reinterpret_cast<const float4*>(bias) + lane);
    float4 r;
    r.x = fmaxf(acc0.x + acc1.x + bb.x, 0.f);
    r.y = fmaxf(acc0.y + acc1.y + bb.y, 0.f);
    r.z = fmaxf(acc0.z + acc1.z + bb.z, 0.f);
    r.w = fmaxf(acc0.w + acc1.w + bb.w, 0.f);
    *(reinterpret_cast<float4*>(&out[(size_t)gw * 128]) + lane) = r;
}

__global__ __launch_bounds__(128)
void agg2_kernel(const float* __restrict__ support, const int* __restrict__ rowoff,
                 const int2* __restrict__ edges,
                 const float* __restrict__ bias, float* __restrict__ out, int N) {
    int gw = (blockIdx.x * blockDim.x + threadIdx.x) >> 5;
    int lane = threadIdx.x & 31;
    if (gw >= N) return;
    int s = rowoff[gw], e = rowoff[gw + 1];
    float2 acc0 = make_float2(0.f, 0.f), acc1 = make_float2(0.f, 0.f);
    int j = s;
    for (; j + 8 <= e; j += 8) {
        int2 ee[8];
        #pragma unroll
        for (int q = 0; q < 8; q++) ee[q] = __ldg(&edges[j + q]);
        float2 v[8];
        #pragma unroll
        for (int q = 0; q < 8; q++)
            v[q] = *(reinterpret_cast<const float2*>(&support[(size_t)ee[q].x * 64]) + lane);
        #pragma unroll
        for (int q = 0; q < 8; q++) {
            float w = __int_as_float(ee[q].y);
            float2* ac = (q & 1) ? &acc1 : &acc0;
            ac->x = fmaf(w, v[q].x, ac->x); ac->y = fmaf(w, v[q].y, ac->y);
        }
    }
    for (; j < e; j++) {
        int2 e0 = __ldg(&edges[j]);
        float w = __int_as_float(e0.y);
        float2 v = *(reinterpret_cast<const float2*>(&support[(size_t)e0.x * 64]) + lane);
        acc0.x = fmaf(w, v.x, acc0.x); acc0.y = fmaf(w, v.y, acc0.y);
    }
    float2 bb = *(reinterpret_cast<const float2*>(bias) + lane);
    float ax = acc0.x + acc1.x + bb.x;
    float ay = acc0.y + acc1.y + bb.y;
    float m = fmaxf(ax, ay);
    #pragma unroll
    for (int o = 16; o; o >>= 1) m = fmaxf(m, __shfl_xor_sync(0xffffffffu, m, o));
    float es = __expf(ax - m) + __expf(ay - m);
    #pragma unroll
    for (int o = 16; o; o >>= 1) es += __shfl_xor_sync(0xffffffffu, es, o);
    float ls = m + __logf(es);
    *(reinterpret_cast<float2*>(&out[(size_t)gw * 64]) + lane) = make_float2(ax - ls, ay - ls);
}

// ---------------------------- launch ----------------------------------------

extern "C" void kernel_launch(void* const* d_in, const int* in_sizes, int n_in,
                              void* d_out, int out_size) {
    const float* feature = (const float*)d_in[0];
    const int*   src     = (const int*)d_in[1];
    const int*   dst     = (const int*)d_in[2];
    const float* ew      = (const float*)d_in[3];
    const float* W1      = (const float*)d_in[4];
    const float* b1      = (const float*)d_in[5];
    const float* W2      = (const float*)d_in[6];
    const float* b2      = (const float*)d_in[7];
    float* out = (float*)d_out;

    const int E    = in_sizes[1];
    const int H    = in_sizes[5];            // 128
    const int F_IN = in_sizes[4] / H;        // 256
    const int N    = in_sizes[0] / F_IN;     // 100000

    float* x1 = out;                          // [N, 128]
    float* x2 = out + (size_t)N * 128;        // [N, 64]

    void *p_sup1, *p_sup2, *p_counts, *p_rowoff, *p_cursor, *p_edges, *p_csum, *p_coff;
    void *p_w1r, *p_w2r;
    cudaGetSymbolAddress(&p_sup1,   g_support1);
    cudaGetSymbolAddress(&p_sup2,   g_support2);
    cudaGetSymbolAddress(&p_counts, g_counts);
    cudaGetSymbolAddress(&p_rowoff, g_rowoff);
    cudaGetSymbolAddress(&p_cursor, g_cursor);
    cudaGetSymbolAddress(&p_edges,  g_edges);
    cudaGetSymbolAddress(&p_csum,   g_csum);
    cudaGetSymbolAddress(&p_coff,   g_coff);
    cudaGetSymbolAddress(&p_w1r,    g_W1r);
    cudaGetSymbolAddress(&p_w2r,    g_W2r);

    constexpr int SMEM1 = 3 * (128 * 36 + 32 * 136) * 4;   // 107520 B
    constexpr int SMEM2 = 3 * (128 * 36 + 32 * 72) * 4;    //  82944 B
    cudaFuncSetAttribute(tf32_gemm_kernel<128>,
                         cudaFuncAttributeMaxDynamicSharedMemorySize, SMEM1);
    cudaFuncSetAttribute(tf32_gemm_kernel<64>,
                         cudaFuncAttributeMaxDynamicSharedMemorySize, SMEM2);

    static cudaStream_t s_side = nullptr;
    static cudaEvent_t ev_fork = nullptr, ev_join = nullptr;
    if (s_side == nullptr) {
        cudaStreamCreateWithFlags(&s_side, cudaStreamNonBlocking);
        cudaEventCreateWithFlags(&ev_fork, cudaEventDisableTiming);
        cudaEventCreateWithFlags(&ev_join, cudaEventDisableTiming);
    }

    const int nch = (N + SCAN_BLOCK - 1) / SCAN_BLOCK;
    const int n1 = F_IN * H, n2 = H * 64;

    // weight rounding first on main stream (GEMM1 needs it)
    round_weights_kernel<<<(n1 + n2 + 255) / 256, 256>>>(W1, W2, (float*)p_w1r, (float*)p_w2r,
                                                         n1, n2);

    // fork: CSR build on side stream, GEMM1 on main stream
    cudaEventRecord(ev_fork, 0);
    cudaStreamWaitEvent(s_side, ev_fork, 0);

    zero_counts_kernel<<<(N + 255) / 256, 256, 0, s_side>>>((int*)p_counts, N);
    hist_kernel<<<(E + 255) / 256, 256, 0, s_side>>>(dst, (int*)p_counts, E);
    chunk_sum_kernel<<<nch, SCAN_BLOCK, 0, s_side>>>((int*)p_counts, (int*)p_csum, N);
    chunk_scan_kernel<<<1, 128, 0, s_side>>>((int*)p_csum, (int*)p_coff, (int*)p_rowoff, nch, N);
    scan_apply_kernel<<<nch, SCAN_BLOCK, 0, s_side>>>((int*)p_counts, (int*)p_coff,
                                                      (int*)p_rowoff, (int*)p_cursor, N);
    scatter_kernel<<<(E + 255) / 256, 256, 0, s_side>>>(src, dst, ew, (int*)p_cursor,
                                                        (int2*)p_edges, E);

    tf32_gemm_kernel<128><<<(N + 127) / 128, 256, SMEM1>>>(feature, (float*)p_w1r,
                                                           (float*)p_sup1, N, F_IN);

    cudaEventRecord(ev_join, s_side);
    cudaStreamWaitEvent(0, ev_join, 0);

    {
        long long threads = (long long)N * 32;
        agg1_kernel<<<(unsigned)((threads + 127) / 128), 128>>>(
            (float*)p_sup1, (int*)p_rowoff, (int2*)p_edges, b1, x1, N);
    }

    tf32_gemm_kernel<64><<<(N + 127) / 128, 256, SMEM2>>>(x1, (float*)p_w2r,
                                                          (float*)p_sup2, N, 128);

    {
        long long threads = (long long)N * 32;
        agg2_kernel<<<(unsigned)((threads + 127) / 128), 128>>>(
            (float*)p_sup2, (int*)p_rowoff, (int2*)p_edges, b2, x2, N);
    }
}

// round 5
// speedup vs baseline: 1.9021x; 1.0964x over previous
#include <cuda_runtime.h>
#include <cuda_fp16.h>
#include <math.h>
#include <stdint.h>

// ---------------------------------------------------------------------------
// GCN_77893526880285 on GB300 (sm_103a)
// R5: support1 stored fp16 (halves the dominant gather traffic),
//     cvt.rna restored on A fragments (removes truncation bias),
//     3-stage cp.async TF32 GEMMs, 8x-unrolled atomic-free aggregation,
//     CSR build overlapped with GEMM1.
// ---------------------------------------------------------------------------

#define NMAX 100352
#define EMAX 1600000
#define NCHUNK_MAX 128
#define SCAN_BLOCK 1024

__device__ __half g_support1h[(size_t)NMAX * 128];  // 25.6 MB
__device__ float  g_support2[(size_t)NMAX * 64];    // 25.6 MB
__device__ float  g_W1r[256 * 128];
__device__ float  g_W2r[128 * 64];
__device__ int    g_counts[NMAX];
__device__ int    g_rowoff[NMAX + 1];
__device__ int    g_cursor[NMAX];
__device__ int2   g_edges[EMAX];
__device__ int    g_csum[NCHUNK_MAX];
__device__ int    g_coff[NCHUNK_MAX];

// ---------------------------- small helpers ---------------------------------

__device__ __forceinline__ uint32_t f2tf32(float v) {
    uint32_t u;
    asm("cvt.rna.tf32.f32 %0, %1;" : "=r"(u) : "f"(v));
    return u;
}

__global__ void round_weights_kernel(const float* __restrict__ W1, const float* __restrict__ W2,
                                     float* __restrict__ W1r, float* __restrict__ W2r,
                                     int n1, int n2) {
    int i = blockIdx.x * blockDim.x + threadIdx.x;
    if (i < n1) W1r[i] = __uint_as_float(f2tf32(W1[i]));
    else if (i < n1 + n2) W2r[i - n1] = __uint_as_float(f2tf32(W2[i - n1]));
}

// ---------------------------- CSR build ------------------------------------

__global__ void zero_counts_kernel(int* __restrict__ counts, int N) {
    int i = blockIdx.x * blockDim.x + threadIdx.x;
    if (i < N) counts[i] = 0;
}

__global__ void hist_kernel(const int* __restrict__ dst, int* __restrict__ counts, int E) {
    int i = blockIdx.x * blockDim.x + threadIdx.x;
    if (i < E) atomicAdd(&counts[dst[i]], 1);
}

__global__ void chunk_sum_kernel(const int* __restrict__ counts, int* __restrict__ csum, int N) {
    int i = blockIdx.x * SCAN_BLOCK + threadIdx.x;
    int v = (i < N) ? counts[i] : 0;
    #pragma unroll
    for (int o = 16; o; o >>= 1) v += __shfl_xor_sync(0xffffffffu, v, o);
    __shared__ int ws[32];
    if ((threadIdx.x & 31) == 0) ws[threadIdx.x >> 5] = v;
    __syncthreads();
    if (threadIdx.x < 32) {
        int x = ws[threadIdx.x];
        #pragma unroll
        for (int o = 16; o; o >>= 1) x += __shfl_xor_sync(0xffffffffu, x, o);
        if (threadIdx.x == 0) csum[blockIdx.x] = x;
    }
}

__global__ void chunk_scan_kernel(const int* __restrict__ csum, int* __restrict__ coff,
                                  int* __restrict__ rowoff, int nch, int N) {
    int tid = threadIdx.x;
    int v = (tid < nch) ? csum[tid] : 0;
    int lane = tid & 31, wid = tid >> 5;
    int x = v;
    #pragma unroll
    for (int o = 1; o < 32; o <<= 1) { int t = __shfl_up_sync(0xffffffffu, x, o); if (lane >= o) x += t; }
    __shared__ int ws[4];
    if (lane == 31) ws[wid] = x;
    __syncthreads();
    int base = 0;
    #pragma unroll
    for (int w = 0; w < 4; w++) if (w < wid) base += ws[w];
    int excl = base + x - v;
    if (tid < nch) coff[tid] = excl;
    if (tid == nch - 1) rowoff[N] = excl + v;
}

__global__ void scan_apply_kernel(const int* __restrict__ counts, const int* __restrict__ coff,
                                  int* __restrict__ rowoff, int* __restrict__ cursor, int N) {
    int tid = threadIdx.x, b = blockIdx.x;
    int i = b * SCAN_BLOCK + tid;
    int v = (i < N) ? counts[i] : 0;
    int lane = tid & 31, wid = tid >> 5;
    int x = v;
    #pragma unroll
    for (int o = 1; o < 32; o <<= 1) { int t = __shfl_up_sync(0xffffffffu, x, o); if (lane >= o) x += t; }
    __shared__ int ws[32];
    if (lane == 31) ws[wid] = x;
    __syncthreads();
    if (wid == 0) {
        int y = ws[lane];
        #pragma unroll
        for (int o = 1; o < 32; o <<= 1) { int t = __shfl_up_sync(0xffffffffu, y, o); if (lane >= o) y += t; }
        ws[lane] = y;
    }
    __syncthreads();
    int base = coff[b] + (wid ? ws[wid - 1] : 0);
    int excl = base + x - v;
    if (i < N) { rowoff[i] = excl; cursor[i] = excl; }
}

__global__ void scatter_kernel(const int* __restrict__ src, const int* __restrict__ dst,
                               const float* __restrict__ ew, int* __restrict__ cursor,
                               int2* __restrict__ edges, int E) {
    int i = blockIdx.x * blockDim.x + threadIdx.x;
    if (i < E) {
        int d = dst[i];
        int p = atomicAdd(&cursor[d], 1);
        edges[p] = make_int2(src[i], __float_as_int(ew[i]));
    }
}

// ---------------- TF32 GEMM, 3-stage cp.async ----------------
// C[M,BN] = A[M,K] @ B[K,BN].  B pre-rounded to tf32; A rounded (rna) in regs.
// OUTH: write fp16 output (row pitch BN halves).

__device__ __forceinline__ void cp16(float* dst_smem, const float* src, int srcsz) {
    uint32_t d = (uint32_t)__cvta_generic_to_shared(dst_smem);
    asm volatile("cp.async.cg.shared.global [%0], [%1], 16, %2;\n"
                 :: "r"(d), "l"(src), "r"(srcsz));
}

__device__ __forceinline__ void mma_tf32(float c[4], const uint32_t a[4],
                                         uint32_t b0, uint32_t b1) {
    asm volatile("mma.sync.aligned.m16n8k8.row.col.f32.tf32.tf32.f32 "
                 "{%0,%1,%2,%3}, {%4,%5,%6,%7}, {%8,%9}, {%0,%1,%2,%3};\n"
                 : "+f"(c[0]), "+f"(c[1]), "+f"(c[2]), "+f"(c[3])
                 : "r"(a[0]), "r"(a[1]), "r"(a[2]), "r"(a[3]), "r"(b0), "r"(b1));
}

template<int BN, bool OUTH>
__global__ __launch_bounds__(256, 2)
void tf32_gemm_kernel(const float* __restrict__ A, const float* __restrict__ B,
                      void* __restrict__ Cv, int M, int K) {
    constexpr int BM = 128, BK = 32, S = 3;
    constexpr int ALD = 36;
    constexpr int BLD = BN + 8;
    constexpr int ASTG = BM * ALD;
    constexpr int BSTG = BK * BLD;
    constexpr int WN = BN / 2;
    constexpr int NT = WN / 8;
    extern __shared__ float sm[];
    float* As = sm;
    float* Bs = sm + S * ASTG;

    const int tid = threadIdx.x;
    const int warp = tid >> 5, lane = tid & 31;
    const int wm = warp >> 1, wn = warp & 1;
    const int lr = lane >> 2, lc = lane & 3;
    const int rowBase = blockIdx.x * BM;

    float c[2][NT][4];
    #pragma unroll
    for (int i = 0; i < 2; i++)
        #pragma unroll
        for (int j = 0; j < NT; j++)
            #pragma unroll
            for (int q = 0; q < 4; q++) c[i][j][q] = 0.f;

    const int ktiles = K / BK;

    auto fill = [&](int t, int stg) {
        int k0 = t * BK;
        #pragma unroll
        for (int it = 0; it < 4; it++) {
            int f = tid + it * 256;
            int row = f >> 3, k4 = f & 7;
            int gr = rowBase + row;
            const float* srcp = A + (size_t)(gr < M ? gr : 0) * K + k0 + k4 * 4;
            cp16(As + stg * ASTG + row * ALD + k4 * 4, srcp, gr < M ? 16 : 0);
        }
        constexpr int BCH = (BK * BN / 4) / 256;
        #pragma unroll
        for (int it = 0; it < BCH; it++) {
            int f = tid + it * 256;
            int krow = f / (BN / 4), nc = f % (BN / 4);
            cp16(Bs + stg * BSTG + krow * BLD + nc * 4,
                 B + (size_t)(k0 + krow) * BN + nc * 4, 16);
        }
        asm volatile("cp.async.commit_group;\n");
    };

    fill(0, 0);
    if (1 < ktiles) fill(1, 1);

    for (int t = 0; t < ktiles; t++) {
        if (t < ktiles - 1) asm volatile("cp.async.wait_group 1;\n");
        else                asm volatile("cp.async.wait_group 0;\n");
        __syncthreads();
        if (t + 2 < ktiles) fill(t + 2, (t + 2) % S);

        const float* Ab = As + (t % S) * ASTG;
        const float* Bb = Bs + (t % S) * BSTG;
        #pragma unroll
        for (int g = 0; g < BK / 8; g++) {
            uint32_t a[2][4];
            #pragma unroll
            for (int mt = 0; mt < 2; mt++) {
                const float* ap = Ab + (wm * 32 + mt * 16 + lr) * ALD + g * 8 + lc;
                a[mt][0] = f2tf32(ap[0]);
                a[mt][2] = f2tf32(ap[4]);
                a[mt][1] = f2tf32(ap[8 * ALD]);
                a[mt][3] = f2tf32(ap[8 * ALD + 4]);
            }
            #pragma unroll
            for (int nt = 0; nt < NT; nt++) {
                const float* bp = Bb + (g * 8 + lc) * BLD + wn * WN + nt * 8 + lr;
                uint32_t b0 = __float_as_uint(bp[0]);
                uint32_t b1 = __float_as_uint(bp[4 * BLD]);
                #pragma unroll
                for (int mt = 0; mt < 2; mt++)
                    mma_tf32(c[mt][nt], a[mt], b0, b1);
            }
        }
        __syncthreads();
    }

    #pragma unroll
    for (int mt = 0; mt < 2; mt++) {
        int r0 = rowBase + wm * 32 + mt * 16 + lr;
        #pragma unroll
        for (int nt = 0; nt < NT; nt++) {
            int col = wn * WN + nt * 8 + 2 * lc;
            if (OUTH) {
                __half* C = (__half*)Cv;
                if (r0 < M)
                    *reinterpret_cast<__half2*>(&C[(size_t)r0 * BN + col]) =
                        __floats2half2_rn(c[mt][nt][0], c[mt][nt][1]);
                if (r0 + 8 < M)
                    *reinterpret_cast<__half2*>(&C[(size_t)(r0 + 8) * BN + col]) =
                        __floats2half2_rn(c[mt][nt][2], c[mt][nt][3]);
            } else {
                float* C = (float*)Cv;
                if (r0 < M)
                    *reinterpret_cast<float2*>(&C[(size_t)r0 * BN + col]) =
                        make_float2(c[mt][nt][0], c[mt][nt][1]);
                if (r0 + 8 < M)
                    *reinterpret_cast<float2*>(&C[(size_t)(r0 + 8) * BN + col]) =
                        make_float2(c[mt][nt][2], c[mt][nt][3]);
            }
        }
    }
}

// ------------------- Aggregation (warp per node, 8x unrolled) ----------------

// layer 1: support fp16 [N,128]; each lane owns 4 features (8B per row).
__global__ __launch_bounds__(128)
void agg1_kernel(const __half* __restrict__ support, const int* __restrict__ rowoff,
                 const int2* __restrict__ edges,
                 const float* __restrict__ bias, float* __restrict__ out, int N) {
    int gw = (blockIdx.x * blockDim.x + threadIdx.x) >> 5;
    int lane = threadIdx.x & 31;
    if (gw >= N) return;
    int s = rowoff[gw], e = rowoff[gw + 1];
    const uint2* base = reinterpret_cast<const uint2*>(support);   // 32 uint2 per row
    float4 acc0 = make_float4(0.f, 0.f, 0.f, 0.f);
    float4 acc1 = make_float4(0.f, 0.f, 0.f, 0.f);
    int j = s;
    for (; j + 8 <= e; j += 8) {
        int2 ee[8];
        #pragma unroll
        for (int q = 0; q < 8; q++) ee[q] = __ldg(&edges[j + q]);
        uint2 v[8];
        #pragma unroll
        for (int q = 0; q < 8; q++) v[q] = __ldg(&base[(size_t)ee[q].x * 32 + lane]);
        #pragma unroll
        for (int q = 0; q < 8; q++) {
            float w = __int_as_float(ee[q].y);
            float2 f0 = __half22float2(*reinterpret_cast<__half2*>(&v[q].x));
            float2 f1 = __half22float2(*reinterpret_cast<__half2*>(&v[q].y));
            float4* ac = (q & 1) ? &acc1 : &acc0;
            ac->x = fmaf(w, f0.x, ac->x); ac->y = fmaf(w, f0.y, ac->y);
            ac->z = fmaf(w, f1.x, ac->z); ac->w = fmaf(w, f1.y, ac->w);
        }
    }
    for (; j < e; j++) {
        int2 e0 = __ldg(&edges[j]);
        float w = __int_as_float(e0.y);
        uint2 v = __ldg(&base[(size_t)e0.x * 32 + lane]);
        float2 f0 = __half22float2(*reinterpret_cast<__half2*>(&v.x));
        float2 f1 = __half22float2(*reinterpret_cast<__half2*>(&v.y));
        acc0.x = fmaf(w, f0.x, acc0.x); acc0.y = fmaf(w, f0.y, acc0.y);
        acc0.z = fmaf(w, f1.x, acc0.z); acc0.w = fmaf(w, f1.y, acc0.w);
    }
    float4 bb = *(reinterpret_cast<const float4*>(bias) + lane);
    float4 r;
    r.x = fmaxf(acc0.x + acc1.x + bb.x, 0.f);
    r.y = fmaxf(acc0.y + acc1.y + bb.y, 0.f);
    r.z = fmaxf(acc0.z + acc1.z + bb.z, 0.f);
    r.w = fmaxf(acc0.w + acc1.w + bb.w, 0.f);
    *(reinterpret_cast<float4*>(&out[(size_t)gw * 128]) + lane) = r;
}

__global__ __launch_bounds__(128)
void agg2_kernel(const float* __restrict__ support, const int* __restrict__ rowoff,
                 const int2* __restrict__ edges,
                 const float* __restrict__ bias, float* __restrict__ out, int N) {
    int gw = (blockIdx.x * blockDim.x + threadIdx.x) >> 5;
    int lane = threadIdx.x & 31;
    if (gw >= N) return;
    int s = rowoff[gw], e = rowoff[gw + 1];
    float2 acc0 = make_float2(0.f, 0.f), acc1 = make_float2(0.f, 0.f);
    int j = s;
    for (; j + 8 <= e; j += 8) {
        int2 ee[8];
        #pragma unroll
        for (int q = 0; q < 8; q++) ee[q] = __ldg(&edges[j + q]);
        float2 v[8];
        #pragma unroll
        for (int q = 0; q < 8; q++)
            v[q] = *(reinterpret_cast<const float2*>(&support[(size_t)ee[q].x * 64]) + lane);
        #pragma unroll
        for (int q = 0; q < 8; q++) {
            float w = __int_as_float(ee[q].y);
            float2* ac = (q & 1) ? &acc1 : &acc0;
            ac->x = fmaf(w, v[q].x, ac->x); ac->y = fmaf(w, v[q].y, ac->y);
        }
    }
    for (; j < e; j++) {
        int2 e0 = __ldg(&edges[j]);
        float w = __int_as_float(e0.y);
        float2 v = *(reinterpret_cast<const float2*>(&support[(size_t)e0.x * 64]) + lane);
        acc0.x = fmaf(w, v.x, acc0.x); acc0.y = fmaf(w, v.y, acc0.y);
    }
    float2 bb = *(reinterpret_cast<const float2*>(bias) + lane);
    float ax = acc0.x + acc1.x + bb.x;
    float ay = acc0.y + acc1.y + bb.y;
    float m = fmaxf(ax, ay);
    #pragma unroll
    for (int o = 16; o; o >>= 1) m = fmaxf(m, __shfl_xor_sync(0xffffffffu, m, o));
    float es = __expf(ax - m) + __expf(ay - m);
    #pragma unroll
    for (int o = 16; o; o >>= 1) es += __shfl_xor_sync(0xffffffffu, es, o);
    float ls = m + __logf(es);
    *(reinterpret_cast<float2*>(&out[(size_t)gw * 64]) + lane) = make_float2(ax - ls, ay - ls);
}

// ---------------------------- launch ----------------------------------------

extern "C" void kernel_launch(void* const* d_in, const int* in_sizes, int n_in,
                              void* d_out, int out_size) {
    const float* feature = (const float*)d_in[0];
    const int*   src     = (const int*)d_in[1];
    const int*   dst     = (const int*)d_in[2];
    const float* ew      = (const float*)d_in[3];
    const float* W1      = (const float*)d_in[4];
    const float* b1      = (const float*)d_in[5];
    const float* W2      = (const float*)d_in[6];
    const float* b2      = (const float*)d_in[7];
    float* out = (float*)d_out;

    const int E    = in_sizes[1];
    const int H    = in_sizes[5];            // 128
    const int F_IN = in_sizes[4] / H;        // 256
    const int N    = in_sizes[0] / F_IN;     // 100000

    float* x1 = out;                          // [N, 128]
    float* x2 = out + (size_t)N * 128;        // [N, 64]

    void *p_sup1h, *p_sup2, *p_counts, *p_rowoff, *p_cursor, *p_edges, *p_csum, *p_coff;
    void *p_w1r, *p_w2r;
    cudaGetSymbolAddress(&p_sup1h,  g_support1h);
    cudaGetSymbolAddress(&p_sup2,   g_support2);
    cudaGetSymbolAddress(&p_counts, g_counts);
    cudaGetSymbolAddress(&p_rowoff, g_rowoff);
    cudaGetSymbolAddress(&p_cursor, g_cursor);
    cudaGetSymbolAddress(&p_edges,  g_edges);
    cudaGetSymbolAddress(&p_csum,   g_csum);
    cudaGetSymbolAddress(&p_coff,   g_coff);
    cudaGetSymbolAddress(&p_w1r,    g_W1r);
    cudaGetSymbolAddress(&p_w2r,    g_W2r);

    constexpr int SMEM1 = 3 * (128 * 36 + 32 * 136) * 4;   // 107520 B
    constexpr int SMEM2 = 3 * (128 * 36 + 32 * 72) * 4;    //  82944 B
    cudaFuncSetAttribute((const void*)tf32_gemm_kernel<128, true>,
                         cudaFuncAttributeMaxDynamicSharedMemorySize, SMEM1);
    cudaFuncSetAttribute((const void*)tf32_gemm_kernel<64, false>,
                         cudaFuncAttributeMaxDynamicSharedMemorySize, SMEM2);

    static cudaStream_t s_side = nullptr;
    static cudaEvent_t ev_fork = nullptr, ev_join = nullptr;
    if (s_side == nullptr) {
        cudaStreamCreateWithFlags(&s_side, cudaStreamNonBlocking);
        cudaEventCreateWithFlags(&ev_fork, cudaEventDisableTiming);
        cudaEventCreateWithFlags(&ev_join, cudaEventDisableTiming);
    }

    const int nch = (N + SCAN_BLOCK - 1) / SCAN_BLOCK;
    const int n1 = F_IN * H, n2 = H * 64;

    round_weights_kernel<<<(n1 + n2 + 255) / 256, 256>>>(W1, W2, (float*)p_w1r, (float*)p_w2r,
                                                         n1, n2);

    // fork: CSR build on side stream, GEMM1 on main stream
    cudaEventRecord(ev_fork, 0);
    cudaStreamWaitEvent(s_side, ev_fork, 0);

    zero_counts_kernel<<<(N + 255) / 256, 256, 0, s_side>>>((int*)p_counts, N);
    hist_kernel<<<(E + 255) / 256, 256, 0, s_side>>>(dst, (int*)p_counts, E);
    chunk_sum_kernel<<<nch, SCAN_BLOCK, 0, s_side>>>((int*)p_counts, (int*)p_csum, N);
    chunk_scan_kernel<<<1, 128, 0, s_side>>>((int*)p_csum, (int*)p_coff, (int*)p_rowoff, nch, N);
    scan_apply_kernel<<<nch, SCAN_BLOCK, 0, s_side>>>((int*)p_counts, (int*)p_coff,
                                                      (int*)p_rowoff, (int*)p_cursor, N);
    scatter_kernel<<<(E + 255) / 256, 256, 0, s_side>>>(src, dst, ew, (int*)p_cursor,
                                                        (int2*)p_edges, E);

    tf32_gemm_kernel<128, true><<<(N + 127) / 128, 256, SMEM1>>>(feature, (float*)p_w1r,
                                                                 p_sup1h, N, F_IN);

    cudaEventRecord(ev_join, s_side);
    cudaStreamWaitEvent(0, ev_join, 0);

    {
        long long threads = (long long)N * 32;
        agg1_kernel<<<(unsigned)((threads + 127) / 128), 128>>>(
            (const __half*)p_sup1h, (int*)p_rowoff, (int2*)p_edges, b1, x1, N);
    }

    tf32_gemm_kernel<64, false><<<(N + 127) / 128, 256, SMEM2>>>(x1, (float*)p_w2r,
                                                                 p_sup2, N, 128);

    {
        long long threads = (long long)N * 32;
        agg2_kernel<<<(unsigned)((threads + 127) / 128), 128>>>(
            (float*)p_sup2, (int*)p_rowoff, (int2*)p_edges, b2, x2, N);
    }
}